// round 13
// baseline (speedup 1.0000x reference)
#include <cuda_runtime.h>
#include <cuda_fp16.h>
#include <math.h>

#define B_     4
#define N_     2048
#define F_     16
#define HID_   32
#define H_     6
#define OUT_   16
#define BN_    (B_*N_)
#define MAXDEG 256
#define FULL   0xffffffffu

// ---------------- scratch ----------------
__device__ int     g_deg[N_];
__device__ int     g_colsP[(size_t)N_ * MAXDEG];        // padded CSR (2 MB)
// h1 fp16 packed: per (node,lane) one uint4 = {h01, h23, h45, pad}
__device__ uint4   g_h1p4[(size_t)BN_ * HID_];          // 4 MB
__device__ float   g_s1f[H_ * BN_];                     // [h][node] layout
__device__ float   g_s2f[H_ * BN_];
__device__ __align__(32) __half g_h2h[BN_ * OUT_];      // 32B rows
__device__ float   g_t1[BN_];
__device__ float   g_t2[BN_];

// ---------------- build padded CSR: float4 + warp scan ----------------
__global__ void k_build(const float* __restrict__ adj) {
    int row  = blockIdx.x * 8 + (threadIdx.x >> 5);
    int lane = threadIdx.x & 31;
    const float4* ar4 = (const float4*)(adj + (size_t)row * N_);
    int* dst = g_colsP + (size_t)row * MAXDEG;
    int w = 0;
    #pragma unroll 4
    for (int it = 0; it < N_ / 128; it++) {           // 128 columns per warp-iter
        int j0 = it * 128 + lane * 4;
        float4 v = ar4[it * 32 + lane];
        bool p0 = (v.x > 0.f) | (j0     == row);
        bool p1 = (v.y > 0.f) | (j0 + 1 == row);
        bool p2 = (v.z > 0.f) | (j0 + 2 == row);
        bool p3 = (v.w > 0.f) | (j0 + 3 == row);
        int c = (int)p0 + (int)p1 + (int)p2 + (int)p3;
        int incl = c;
        #pragma unroll
        for (int d = 1; d < 32; d <<= 1) {
            int t = __shfl_up_sync(FULL, incl, d);
            if (lane >= d) incl += t;
        }
        int pos = w + incl - c;                        // exclusive
        if (p0 && pos < MAXDEG) dst[pos++] = j0;
        if (p1 && pos < MAXDEG) dst[pos++] = j0 + 1;
        if (p2 && pos < MAXDEG) dst[pos++] = j0 + 2;
        if (p3 && pos < MAXDEG) dst[pos++] = j0 + 3;
        w += __shfl_sync(FULL, incl, 31);
    }
    if (lane == 0) g_deg[row] = min(w, MAXDEG);
}

// ---------------- layer 1 linear: warp per node, all 6 heads ----------------
__global__ void k_l1_linear(const float* __restrict__ x,
                            const float* __restrict__ W1,
                            const float* __restrict__ a1) {
    __shared__ float sW[H_ * F_ * HID_];   // 12 KB
    __shared__ float sa[H_ * 2 * HID_];
    int tid = threadIdx.x;
    for (int t = tid; t < H_ * F_ * HID_; t += 256) sW[t] = W1[t];
    for (int t = tid; t < H_ * 2 * HID_;  t += 256) sa[t] = a1[t];
    __syncthreads();

    int wslot = tid >> 5, lane = tid & 31;
    int row = blockIdx.x * 8 + wslot;

    float xv = (lane < F_) ? x[(size_t)row * F_ + lane] : 0.f;
    float acc[H_] = {0.f, 0.f, 0.f, 0.f, 0.f, 0.f};
    #pragma unroll
    for (int k = 0; k < F_; k++) {
        float xk = __shfl_sync(FULL, xv, k);
        #pragma unroll
        for (int h = 0; h < H_; h++)
            acc[h] = fmaf(xk, sW[h * F_ * HID_ + k * HID_ + lane], acc[h]);
    }
    {
        __half2 h01 = __floats2half2_rn(acc[0], acc[1]);
        __half2 h23 = __floats2half2_rn(acc[2], acc[3]);
        __half2 h45 = __floats2half2_rn(acc[4], acc[5]);
        uint4 pk;
        pk.x = *(unsigned*)&h01; pk.y = *(unsigned*)&h23;
        pk.z = *(unsigned*)&h45; pk.w = 0u;
        g_h1p4[(size_t)row * HID_ + lane] = pk;
    }
    #pragma unroll
    for (int h = 0; h < H_; h++) {
        float p1 = acc[h] * sa[h * 2 * HID_ + lane];
        float p2 = acc[h] * sa[h * 2 * HID_ + HID_ + lane];
        #pragma unroll
        for (int d = 16; d; d >>= 1) {
            p1 += __shfl_xor_sync(FULL, p1, d);
            p2 += __shfl_xor_sync(FULL, p2, d);
        }
        if (lane == 0) {
            g_s1f[h * BN_ + row] = p1;     // [h][node] layout
            g_s2f[h * BN_ + row] = p2;
        }
    }
}

// ---------------- fused layer-1 attention + ELU + layer-2 linear ----------------
// block = 512 thr = 16 warps = 16 rows of one b. Dynamic smem:
//   [0)      half  s2h[6][2048]   24576 B
//   [24576)  float sW2[192*17]    13056 B
//   [37632)  float sa2[32]          128 B
//   [37760)  float sw[16][32][8]  16384 B  (per-neighbor head weights; reused for x1)
//   [54144)  int   sj[16][32]      2048 B
#define SM1_S2  0
#define SM1_W2  24576
#define SM1_A2  37632
#define SM1_SW  37760
#define SM1_SJ  54144
#define SM1_TOT 56192

__global__ void __launch_bounds__(512, 2) k_l1_attn(const float* __restrict__ W2,
                                                    const float* __restrict__ a2) {
    extern __shared__ char smem[];
    __half* s2h = (__half*)(smem + SM1_S2);
    float*  sW2 = (float*)(smem + SM1_W2);
    float*  sa2 = (float*)(smem + SM1_A2);
    float (*sw)[32][8] = (float (*)[32][8])(smem + SM1_SW);
    int   (*sj)[32]    = (int (*)[32])(smem + SM1_SJ);

    int tid = threadIdx.x;
    int b  = blockIdx.x >> 7;                 // 128 blocks per b
    int i0 = (blockIdx.x & 127) * 16;

    for (int t = tid; t < H_ * N_; t += 512) {
        int h = t >> 11, n = t & (N_ - 1);
        s2h[t] = __float2half(g_s2f[h * BN_ + b * N_ + n]);
    }
    for (int t = tid; t < 192 * 16; t += 512) sW2[(t >> 4) * 17 + (t & 15)] = W2[t];
    if (tid < 32) sa2[tid] = a2[tid];
    __syncthreads();

    int w = tid >> 5, lane = tid & 31;
    int i = i0 + w;
    int node_i = b * N_ + i;
    int deg = g_deg[i];
    const int* cols = g_colsP + (size_t)i * MAXDEG;

    float s1v[6];
    #pragma unroll
    for (int h = 0; h < 6; h++) s1v[h] = g_s1f[h * BN_ + node_i];

    const uint4* fp4 = g_h1p4 + (size_t)b * N_ * HID_;

    float acc[6] = {0.f, 0.f, 0.f, 0.f, 0.f, 0.f};
    float den[6] = {0.f, 0.f, 0.f, 0.f, 0.f, 0.f};

    for (int base = 0; base < deg; base += 32) {
        int lim = min(32, deg - base);
        if (lane < lim) {
            int j = cols[base + lane];
            sj[w][lane] = j;
            float wt6[6];
            #pragma unroll
            for (int h = 0; h < 6; h++) {
                float e = s1v[h] + __half2float(s2h[h * N_ + j]);
                e = e > 0.f ? e : 0.2f * e;      // LeakyReLU
                float wt = __expf(e);            // no max-shift (|e| small, fp32 safe)
                den[h] += wt;
                wt6[h] = wt;
            }
            *(float4*)&sw[w][lane][0] = make_float4(wt6[0], wt6[1], wt6[2], wt6[3]);
            *(float2*)&sw[w][lane][4] = make_float2(wt6[4], wt6[5]);
        }
        __syncwarp();
        #define GFMA(U) {                                                  \
            float4 w03 = *(const float4*)&sw[w][t0 + U][0];                \
            float2 w45 = *(const float2*)&sw[w][t0 + U][4];                \
            float2 f0 = __half22float2(*(const __half2*)&va[U].x);         \
            float2 f1 = __half22float2(*(const __half2*)&va[U].y);         \
            float2 f2 = __half22float2(*(const __half2*)&va[U].z);         \
            acc[0] = fmaf(w03.x, f0.x, acc[0]);                            \
            acc[1] = fmaf(w03.y, f0.y, acc[1]);                            \
            acc[2] = fmaf(w03.z, f1.x, acc[2]);                            \
            acc[3] = fmaf(w03.w, f1.y, acc[3]);                            \
            acc[4] = fmaf(w45.x, f2.x, acc[4]);                            \
            acc[5] = fmaf(w45.y, f2.y, acc[5]); }
        if (lim == 32) {
            #pragma unroll
            for (int t0 = 0; t0 < 32; t0 += 4) {       // batch 4: 4 LDG.128 in flight
                uint4 va[4];
                va[0] = fp4[sj[w][t0]     * HID_ + lane];
                va[1] = fp4[sj[w][t0 + 1] * HID_ + lane];
                va[2] = fp4[sj[w][t0 + 2] * HID_ + lane];
                va[3] = fp4[sj[w][t0 + 3] * HID_ + lane];
                GFMA(0) GFMA(1) GFMA(2) GFMA(3)
            }
        } else {
            for (int t0 = 0; t0 < lim; t0++) {
                uint4 va[1];
                va[0] = fp4[sj[w][t0] * HID_ + lane];
                GFMA(0)
            }
        }
        #undef GFMA
        __syncwarp();
    }
    #pragma unroll
    for (int h = 0; h < 6; h++) {
        #pragma unroll
        for (int d = 16; d; d >>= 1) den[h] += __shfl_xor_sync(FULL, den[h], d);
    }
    // ELU(x1) into the (now free) sw slice: x1[h*32+lane] = v[h]
    #pragma unroll
    for (int h = 0; h < 6; h++) {
        float v = acc[h] / den[h];
        v = v > 0.f ? v : expm1f(v);
        sw[w][lane][h] = v;
    }
    __syncwarp();

    // layer-2 linear: lane -> output o over a 96-wide k half
    int o = lane & 15, half = lane >> 4;
    int cbase = half * 96;
    float hacc = 0.f;
    #pragma unroll
    for (int c = 0; c < 96; c++) {
        int cc = cbase + c;
        hacc = fmaf(sw[w][cc & 31][cc >> 5], sW2[cc * 17 + o], hacc);
    }
    hacc += __shfl_xor_sync(FULL, hacc, 16);      // combine k-halves: all lanes have h2[o]
    if (lane < 16) g_h2h[node_i * OUT_ + o] = __float2half(hacc);

    float q1 = hacc * sa2[o];
    float q2 = hacc * sa2[OUT_ + o];
    #pragma unroll
    for (int d = 8; d; d >>= 1) {
        q1 += __shfl_xor_sync(FULL, q1, d, 16);
        q2 += __shfl_xor_sync(FULL, q2, d, 16);
    }
    if (lane == 0) {
        g_t1[node_i] = q1;
        g_t2[node_i] = q2;
    }
}

// ---------------- layer-2 attention: lane-per-neighbor, staged t2, 2-way chains ----------------
#define L2W 8
__global__ void __launch_bounds__(256) k_l2_attn(float* __restrict__ out) {
    __shared__ float st2[N_];              // 8 KB (all 8 warps share b)
    __shared__ float red[L2W][16 * 33];    // padded transpose for final reduction (16.5 KB)
    int w = threadIdx.x >> 5, lane = threadIdx.x & 31;
    int gw = blockIdx.x * L2W + w;          // warp per (b, i); 2048 % 8 == 0 -> same b per block
    int i = gw & (N_ - 1), b = gw >> 11;
    int node_i = b * N_ + i;

    for (int t = threadIdx.x; t < N_; t += 256) st2[t] = g_t2[b * N_ + t];
    __syncthreads();

    int deg = g_deg[i];
    const int* cols = g_colsP + (size_t)i * MAXDEG;
    float s1i = g_t1[node_i];
    const uint4* h2b = (const uint4*)(g_h2h + (size_t)b * N_ * OUT_);

    float acc[16];
    #pragma unroll
    for (int o = 0; o < 16; o++) acc[o] = 0.f;
    float den = 0.f;

    #define ACC16(WT, VA, VB) {                                                              \
        float2 f;                                                                            \
        f = __half22float2(*(const __half2*)&VA.x); acc[0]  = fmaf(WT, f.x, acc[0]);  acc[1]  = fmaf(WT, f.y, acc[1]);  \
        f = __half22float2(*(const __half2*)&VA.y); acc[2]  = fmaf(WT, f.x, acc[2]);  acc[3]  = fmaf(WT, f.y, acc[3]);  \
        f = __half22float2(*(const __half2*)&VA.z); acc[4]  = fmaf(WT, f.x, acc[4]);  acc[5]  = fmaf(WT, f.y, acc[5]);  \
        f = __half22float2(*(const __half2*)&VA.w); acc[6]  = fmaf(WT, f.x, acc[6]);  acc[7]  = fmaf(WT, f.y, acc[7]);  \
        f = __half22float2(*(const __half2*)&VB.x); acc[8]  = fmaf(WT, f.x, acc[8]);  acc[9]  = fmaf(WT, f.y, acc[9]);  \
        f = __half22float2(*(const __half2*)&VB.y); acc[10] = fmaf(WT, f.x, acc[10]); acc[11] = fmaf(WT, f.y, acc[11]); \
        f = __half22float2(*(const __half2*)&VB.z); acc[12] = fmaf(WT, f.x, acc[12]); acc[13] = fmaf(WT, f.y, acc[13]); \
        f = __half22float2(*(const __half2*)&VB.w); acc[14] = fmaf(WT, f.x, acc[14]); acc[15] = fmaf(WT, f.y, acc[15]); }

    int t = lane;
    for (; t + 32 < deg; t += 64) {          // two independent neighbor chains
        int j1 = __ldg(cols + t);
        int j2 = __ldg(cols + t + 32);
        uint4 va1 = __ldg(h2b + j1 * 2);
        uint4 vb1 = __ldg(h2b + j1 * 2 + 1);
        uint4 va2 = __ldg(h2b + j2 * 2);
        uint4 vb2 = __ldg(h2b + j2 * 2 + 1);
        float e1 = s1i + st2[j1];
        e1 = e1 > 0.f ? e1 : 0.2f * e1;
        float wt1 = __expf(e1);
        float e2 = s1i + st2[j2];
        e2 = e2 > 0.f ? e2 : 0.2f * e2;
        float wt2 = __expf(e2);
        den += wt1 + wt2;
        ACC16(wt1, va1, vb1)
        ACC16(wt2, va2, vb2)
    }
    if (t < deg) {
        int j1 = __ldg(cols + t);
        uint4 va1 = __ldg(h2b + j1 * 2);
        uint4 vb1 = __ldg(h2b + j1 * 2 + 1);
        float e1 = s1i + st2[j1];
        e1 = e1 > 0.f ? e1 : 0.2f * e1;
        float wt1 = __expf(e1);
        den += wt1;
        ACC16(wt1, va1, vb1)
    }
    #undef ACC16

    #pragma unroll
    for (int d = 16; d; d >>= 1) den += __shfl_xor_sync(FULL, den, d);

    // transpose-reduce: lane writes its 16 accs, then 16 lanes sum 32 each
    float* rw = red[w];
    #pragma unroll
    for (int o = 0; o < 16; o++) rw[o * 33 + lane] = acc[o];
    __syncwarp();
    if (lane < 16) {
        float s = 0.f;
        #pragma unroll
        for (int k = 0; k < 32; k++) s += rw[lane * 33 + k];
        float v = s / den;
        v = v > 0.f ? v : expm1f(v);          // ELU
        out[(size_t)node_i * OUT_ + lane] = v;
    }
}

// ---------------- launch ----------------
extern "C" void kernel_launch(void* const* d_in, const int* in_sizes, int n_in,
                              void* d_out, int out_size) {
    const float* flow_x = (const float*)d_in[0];   // [4,2048,16]
    const float* adj    = (const float*)d_in[1];   // [2048,2048]
    const float* W1     = (const float*)d_in[2];   // [6,16,32]
    const float* a1     = (const float*)d_in[3];   // [6,64,1]
    const float* W2     = (const float*)d_in[4];   // [192,16]
    const float* a2     = (const float*)d_in[5];   // [32,1]
    float* out = (float*)d_out;

    cudaFuncSetAttribute(k_l1_attn, cudaFuncAttributeMaxDynamicSharedMemorySize, SM1_TOT);

    k_build<<<N_ / 8, 256>>>(adj);
    k_l1_linear<<<BN_ / 8, 256>>>(flow_x, W1, a1);
    k_l1_attn<<<BN_ / 16, 512, SM1_TOT>>>(W2, a2);
    k_l2_attn<<<BN_ / L2W, 256>>>(out);
}

// round 14
// speedup vs baseline: 1.0513x; 1.0513x over previous
#include <cuda_runtime.h>
#include <cuda_fp16.h>
#include <math.h>

#define B_     4
#define N_     2048
#define F_     16
#define HID_   32
#define H_     6
#define OUT_   16
#define BN_    (B_*N_)
#define MAXDEG 256
#define FULL   0xffffffffu

// ---------------- scratch ----------------
__device__ int     g_deg[N_];
__device__ int     g_colsP[(size_t)N_ * MAXDEG];        // padded CSR (2 MB)
// h1 fp16 packed: per (node,lane): heads 0-3 in uint2, heads 4-5 in uint
__device__ uint2   g_h1a[(size_t)BN_ * HID_];           // 2 MB
__device__ unsigned g_h1b[(size_t)BN_ * HID_];          // 1 MB
__device__ float   g_s1f[H_ * BN_];                     // [h][node] layout
__device__ float   g_s2f[H_ * BN_];
__device__ __align__(32) __half g_h2h[BN_ * OUT_];      // 32B rows
__device__ float   g_t1[BN_];
__device__ float   g_t2[BN_];

// ---------------- build padded CSR: float4 + warp scan ----------------
__global__ void k_build(const float* __restrict__ adj) {
    int row  = blockIdx.x * 8 + (threadIdx.x >> 5);
    int lane = threadIdx.x & 31;
    const float4* ar4 = (const float4*)(adj + (size_t)row * N_);
    int* dst = g_colsP + (size_t)row * MAXDEG;
    int w = 0;
    #pragma unroll 4
    for (int it = 0; it < N_ / 128; it++) {           // 128 columns per warp-iter
        int j0 = it * 128 + lane * 4;
        float4 v = ar4[it * 32 + lane];
        bool p0 = (v.x > 0.f) | (j0     == row);
        bool p1 = (v.y > 0.f) | (j0 + 1 == row);
        bool p2 = (v.z > 0.f) | (j0 + 2 == row);
        bool p3 = (v.w > 0.f) | (j0 + 3 == row);
        int c = (int)p0 + (int)p1 + (int)p2 + (int)p3;
        int incl = c;
        #pragma unroll
        for (int d = 1; d < 32; d <<= 1) {
            int t = __shfl_up_sync(FULL, incl, d);
            if (lane >= d) incl += t;
        }
        int pos = w + incl - c;                        // exclusive
        if (p0 && pos < MAXDEG) dst[pos++] = j0;
        if (p1 && pos < MAXDEG) dst[pos++] = j0 + 1;
        if (p2 && pos < MAXDEG) dst[pos++] = j0 + 2;
        if (p3 && pos < MAXDEG) dst[pos++] = j0 + 3;
        w += __shfl_sync(FULL, incl, 31);
    }
    if (lane == 0) g_deg[row] = min(w, MAXDEG);
}

// ---------------- layer 1 linear: warp per node, all 6 heads ----------------
__global__ void k_l1_linear(const float* __restrict__ x,
                            const float* __restrict__ W1,
                            const float* __restrict__ a1) {
    __shared__ float sW[H_ * F_ * HID_];   // 12 KB
    __shared__ float sa[H_ * 2 * HID_];
    int tid = threadIdx.x;
    for (int t = tid; t < H_ * F_ * HID_; t += 256) sW[t] = W1[t];
    for (int t = tid; t < H_ * 2 * HID_;  t += 256) sa[t] = a1[t];
    __syncthreads();

    int wslot = tid >> 5, lane = tid & 31;
    int row = blockIdx.x * 8 + wslot;

    float xv = (lane < F_) ? x[(size_t)row * F_ + lane] : 0.f;
    float acc[H_] = {0.f, 0.f, 0.f, 0.f, 0.f, 0.f};
    #pragma unroll
    for (int k = 0; k < F_; k++) {
        float xk = __shfl_sync(FULL, xv, k);
        #pragma unroll
        for (int h = 0; h < H_; h++)
            acc[h] = fmaf(xk, sW[h * F_ * HID_ + k * HID_ + lane], acc[h]);
    }
    {
        __half2 h01 = __floats2half2_rn(acc[0], acc[1]);
        __half2 h23 = __floats2half2_rn(acc[2], acc[3]);
        __half2 h45 = __floats2half2_rn(acc[4], acc[5]);
        uint2 a; a.x = *(unsigned*)&h01; a.y = *(unsigned*)&h23;
        g_h1a[(size_t)row * HID_ + lane] = a;
        g_h1b[(size_t)row * HID_ + lane] = *(unsigned*)&h45;
    }
    #pragma unroll
    for (int h = 0; h < H_; h++) {
        float p1 = acc[h] * sa[h * 2 * HID_ + lane];
        float p2 = acc[h] * sa[h * 2 * HID_ + HID_ + lane];
        #pragma unroll
        for (int d = 16; d; d >>= 1) {
            p1 += __shfl_xor_sync(FULL, p1, d);
            p2 += __shfl_xor_sync(FULL, p2, d);
        }
        if (lane == 0) {
            g_s1f[h * BN_ + row] = p1;     // [h][node] layout
            g_s2f[h * BN_ + row] = p2;
        }
    }
}

// ---------------- fused layer-1 attention + ELU + layer-2 linear ----------------
// block = 512 thr = 16 warps = 16 rows of one b. Dynamic smem:
//   [0)      half  s2h[6][2048]   24576 B
//   [24576)  float sW2[192*17]    13056 B
//   [37632)  float sa2[32]          128 B
//   [37760)  float sw[16][32][8]  16384 B  (per-neighbor head weights; reused for x1)
//   [54144)  int   sj[16][32]      2048 B
#define SM1_S2  0
#define SM1_W2  24576
#define SM1_A2  37632
#define SM1_SW  37760
#define SM1_SJ  54144
#define SM1_TOT 56192

__global__ void __launch_bounds__(512, 2) k_l1_attn(const float* __restrict__ W2,
                                                    const float* __restrict__ a2) {
    extern __shared__ char smem[];
    __half* s2h = (__half*)(smem + SM1_S2);
    float*  sW2 = (float*)(smem + SM1_W2);
    float*  sa2 = (float*)(smem + SM1_A2);
    float (*sw)[32][8] = (float (*)[32][8])(smem + SM1_SW);
    int   (*sj)[32]    = (int (*)[32])(smem + SM1_SJ);

    int tid = threadIdx.x;
    int b  = blockIdx.x >> 7;                 // 128 blocks per b
    int i0 = (blockIdx.x & 127) * 16;

    for (int t = tid; t < H_ * N_; t += 512) {
        int h = t >> 11, n = t & (N_ - 1);
        s2h[t] = __float2half(g_s2f[h * BN_ + b * N_ + n]);
    }
    for (int t = tid; t < 192 * 16; t += 512) sW2[(t >> 4) * 17 + (t & 15)] = W2[t];
    if (tid < 32) sa2[tid] = a2[tid];
    __syncthreads();

    int w = tid >> 5, lane = tid & 31;
    int i = i0 + w;
    int node_i = b * N_ + i;
    int deg = g_deg[i];
    const int* cols = g_colsP + (size_t)i * MAXDEG;

    float s1v[6];
    #pragma unroll
    for (int h = 0; h < 6; h++) s1v[h] = g_s1f[h * BN_ + node_i];

    const uint2*    fa = g_h1a + (size_t)b * N_ * HID_;
    const unsigned* fb = g_h1b + (size_t)b * N_ * HID_;

    float acc[6] = {0.f, 0.f, 0.f, 0.f, 0.f, 0.f};
    float den[6] = {0.f, 0.f, 0.f, 0.f, 0.f, 0.f};

    for (int base = 0; base < deg; base += 32) {
        int lim = min(32, deg - base);
        if (lane < lim) {
            int j = cols[base + lane];
            sj[w][lane] = j;
            float wt6[6];
            #pragma unroll
            for (int h = 0; h < 6; h++) {
                float e = s1v[h] + __half2float(s2h[h * N_ + j]);
                e = e > 0.f ? e : 0.2f * e;      // LeakyReLU
                float wt = __expf(e);            // no max-shift (|e| small, fp32 safe)
                den[h] += wt;
                wt6[h] = wt;
            }
            *(float4*)&sw[w][lane][0] = make_float4(wt6[0], wt6[1], wt6[2], wt6[3]);
            *(float2*)&sw[w][lane][4] = make_float2(wt6[4], wt6[5]);
        }
        __syncwarp();
        #define GFMA(U) {                                                  \
            float4 w03 = *(const float4*)&sw[w][t0 + U][0];                \
            float2 w45 = *(const float2*)&sw[w][t0 + U][4];                \
            float2 f0 = __half22float2(*(const __half2*)&va[U].x);         \
            float2 f1 = __half22float2(*(const __half2*)&va[U].y);         \
            float2 f2 = __half22float2(*(const __half2*)&vb[U]);           \
            acc[0] = fmaf(w03.x, f0.x, acc[0]);                            \
            acc[1] = fmaf(w03.y, f0.y, acc[1]);                            \
            acc[2] = fmaf(w03.z, f1.x, acc[2]);                            \
            acc[3] = fmaf(w03.w, f1.y, acc[3]);                            \
            acc[4] = fmaf(w45.x, f2.x, acc[4]);                            \
            acc[5] = fmaf(w45.y, f2.y, acc[5]); }
        if (lim == 32) {
            #pragma unroll
            for (int t0 = 0; t0 < 32; t0 += 4) {       // batch 4: 8 LDGs in flight
                int nb0 = sj[w][t0]     * HID_ + lane;
                int nb1 = sj[w][t0 + 1] * HID_ + lane;
                int nb2 = sj[w][t0 + 2] * HID_ + lane;
                int nb3 = sj[w][t0 + 3] * HID_ + lane;
                uint2 va[4]; unsigned vb[4];
                va[0] = fa[nb0]; va[1] = fa[nb1]; va[2] = fa[nb2]; va[3] = fa[nb3];
                vb[0] = fb[nb0]; vb[1] = fb[nb1]; vb[2] = fb[nb2]; vb[3] = fb[nb3];
                GFMA(0) GFMA(1) GFMA(2) GFMA(3)
            }
        } else {
            for (int t0 = 0; t0 < lim; t0++) {
                int nb0 = sj[w][t0] * HID_ + lane;
                uint2 va[1]; unsigned vb[1];
                va[0] = fa[nb0]; vb[0] = fb[nb0];
                GFMA(0)
            }
        }
        #undef GFMA
        __syncwarp();
    }
    #pragma unroll
    for (int h = 0; h < 6; h++) {
        #pragma unroll
        for (int d = 16; d; d >>= 1) den[h] += __shfl_xor_sync(FULL, den[h], d);
    }
    // ELU(x1) into the (now free) sw slice: x1[h*32+lane] = v[h]
    #pragma unroll
    for (int h = 0; h < 6; h++) {
        float v = acc[h] / den[h];
        v = v > 0.f ? v : expm1f(v);
        sw[w][lane][h] = v;
    }
    __syncwarp();

    // layer-2 linear: lane -> output o over a 96-wide k half
    int o = lane & 15, half = lane >> 4;
    int cbase = half * 96;
    float hacc = 0.f;
    #pragma unroll
    for (int c = 0; c < 96; c++) {
        int cc = cbase + c;
        hacc = fmaf(sw[w][cc & 31][cc >> 5], sW2[cc * 17 + o], hacc);
    }
    hacc += __shfl_xor_sync(FULL, hacc, 16);      // combine k-halves: all lanes have h2[o]
    if (lane < 16) g_h2h[node_i * OUT_ + o] = __float2half(hacc);

    float q1 = hacc * sa2[o];
    float q2 = hacc * sa2[OUT_ + o];
    #pragma unroll
    for (int d = 8; d; d >>= 1) {
        q1 += __shfl_xor_sync(FULL, q1, d, 16);
        q2 += __shfl_xor_sync(FULL, q2, d, 16);
    }
    if (lane == 0) {
        g_t1[node_i] = q1;
        g_t2[node_i] = q2;
    }
}

// ---------------- layer-2 attention v3: lane-per-neighbor, smem-staged h2 ----------------
// block = 512 thr = 16 warps = 16 rows of one b. Dynamic smem:
//   [0)      __half sh2[2048*16]  65536 B  (reused as reduction scratch after gather)
//   [65536)  float  st2[2048]      8192 B
#define SM2_H2  0
#define SM2_T2  65536
#define SM2_TOT 73728

__global__ void __launch_bounds__(512, 2) k_l2_attn(float* __restrict__ out) {
    extern __shared__ char smem[];
    __half* sh2 = (__half*)(smem + SM2_H2);
    float*  st2 = (float*)(smem + SM2_T2);

    int tid = threadIdx.x;
    int b  = blockIdx.x >> 7;                 // 128 blocks per b
    int i0 = (blockIdx.x & 127) * 16;

    {   // stage h2 (fp16, uint4 copy) and t2 for this b
        const uint4* src = (const uint4*)(g_h2h + (size_t)b * N_ * OUT_);
        uint4* dst = (uint4*)sh2;
        for (int t = tid; t < N_ * OUT_ * 2 / 16; t += 512) dst[t] = src[t];
        for (int t = tid; t < N_; t += 512) st2[t] = g_t2[b * N_ + t];
    }
    __syncthreads();

    int w = tid >> 5, lane = tid & 31;
    int i = i0 + w;
    int node_i = b * N_ + i;
    int deg = g_deg[i];
    const int* cols = g_colsP + (size_t)i * MAXDEG;
    float s1i = g_t1[node_i];
    const uint4* sh2v = (const uint4*)sh2;     // [node*2 + half]

    float acc[16];
    #pragma unroll
    for (int o = 0; o < 16; o++) acc[o] = 0.f;
    float den = 0.f;

    for (int t = lane; t < deg; t += 32) {     // each lane owns its neighbors
        int j = __ldg(cols + t);
        float e = s1i + st2[j];
        e = e > 0.f ? e : 0.2f * e;            // LeakyReLU
        float wt = __expf(e);
        den += wt;
        uint4 va = sh2v[j * 2];
        uint4 vb = sh2v[j * 2 + 1];
        float2 f;
        f = __half22float2(*(const __half2*)&va.x); acc[0]  = fmaf(wt, f.x, acc[0]);  acc[1]  = fmaf(wt, f.y, acc[1]);
        f = __half22float2(*(const __half2*)&va.y); acc[2]  = fmaf(wt, f.x, acc[2]);  acc[3]  = fmaf(wt, f.y, acc[3]);
        f = __half22float2(*(const __half2*)&va.z); acc[4]  = fmaf(wt, f.x, acc[4]);  acc[5]  = fmaf(wt, f.y, acc[5]);
        f = __half22float2(*(const __half2*)&va.w); acc[6]  = fmaf(wt, f.x, acc[6]);  acc[7]  = fmaf(wt, f.y, acc[7]);
        f = __half22float2(*(const __half2*)&vb.x); acc[8]  = fmaf(wt, f.x, acc[8]);  acc[9]  = fmaf(wt, f.y, acc[9]);
        f = __half22float2(*(const __half2*)&vb.y); acc[10] = fmaf(wt, f.x, acc[10]); acc[11] = fmaf(wt, f.y, acc[11]);
        f = __half22float2(*(const __half2*)&vb.z); acc[12] = fmaf(wt, f.x, acc[12]); acc[13] = fmaf(wt, f.y, acc[13]);
        f = __half22float2(*(const __half2*)&vb.w); acc[14] = fmaf(wt, f.x, acc[14]); acc[15] = fmaf(wt, f.y, acc[15]);
    }
    #pragma unroll
    for (int d = 16; d; d >>= 1) den += __shfl_xor_sync(FULL, den, d);

    // all gathers done -> sh2 region free; reuse as reduction scratch
    __syncthreads();
    float* red = (float*)sh2 + w * (16 * 33);   // 528 floats per warp, 33.8 KB total
    #pragma unroll
    for (int o = 0; o < 16; o++) red[o * 33 + lane] = acc[o];
    __syncwarp();
    if (lane < 16) {
        float s = 0.f;
        #pragma unroll
        for (int k = 0; k < 32; k++) s += red[lane * 33 + k];
        float v = s / den;
        v = v > 0.f ? v : expm1f(v);            // ELU
        out[(size_t)node_i * OUT_ + lane] = v;
    }
}

// ---------------- launch ----------------
extern "C" void kernel_launch(void* const* d_in, const int* in_sizes, int n_in,
                              void* d_out, int out_size) {
    const float* flow_x = (const float*)d_in[0];   // [4,2048,16]
    const float* adj    = (const float*)d_in[1];   // [2048,2048]
    const float* W1     = (const float*)d_in[2];   // [6,16,32]
    const float* a1     = (const float*)d_in[3];   // [6,64,1]
    const float* W2     = (const float*)d_in[4];   // [192,16]
    const float* a2     = (const float*)d_in[5];   // [32,1]
    float* out = (float*)d_out;

    cudaFuncSetAttribute(k_l1_attn, cudaFuncAttributeMaxDynamicSharedMemorySize, SM1_TOT);
    cudaFuncSetAttribute(k_l2_attn, cudaFuncAttributeMaxDynamicSharedMemorySize, SM2_TOT);

    k_build<<<N_ / 8, 256>>>(adj);
    k_l1_linear<<<BN_ / 8, 256>>>(flow_x, W1, a1);
    k_l1_attn<<<BN_ / 16, 512, SM1_TOT>>>(W2, a2);
    k_l2_attn<<<BN_ / 16, 512, SM2_TOT>>>(out);
}

// round 15
// speedup vs baseline: 1.0668x; 1.0147x over previous
#include <cuda_runtime.h>
#include <cuda_fp16.h>
#include <math.h>

#define B_     4
#define N_     2048
#define F_     16
#define HID_   32
#define H_     6
#define OUT_   16
#define BN_    (B_*N_)
#define MAXDEG 256
#define FULL   0xffffffffu

// ---------------- scratch ----------------
__device__ int     g_deg[N_];
__device__ int     g_colsP[(size_t)N_ * MAXDEG];        // padded CSR (2 MB)
// h1 fp16 packed: per (node,lane): heads 0-3 in uint2, heads 4-5 in uint
__device__ uint2   g_h1a[(size_t)BN_ * HID_];           // 2 MB
__device__ unsigned g_h1b[(size_t)BN_ * HID_];          // 1 MB
__device__ float   g_s1f[H_ * BN_];                     // [h][node] layout
__device__ float   g_s2f[H_ * BN_];
__device__ __align__(32) __half g_h2h[BN_ * OUT_];      // 32B rows
__device__ float   g_t1[BN_];
__device__ float   g_t2[BN_];

// ---------------- build padded CSR: float4 + warp scan ----------------
__global__ void k_build(const float* __restrict__ adj) {
    int row  = blockIdx.x * 8 + (threadIdx.x >> 5);
    int lane = threadIdx.x & 31;
    const float4* ar4 = (const float4*)(adj + (size_t)row * N_);
    int* dst = g_colsP + (size_t)row * MAXDEG;
    int w = 0;
    #pragma unroll 4
    for (int it = 0; it < N_ / 128; it++) {           // 128 columns per warp-iter
        int j0 = it * 128 + lane * 4;
        float4 v = ar4[it * 32 + lane];
        bool p0 = (v.x > 0.f) | (j0     == row);
        bool p1 = (v.y > 0.f) | (j0 + 1 == row);
        bool p2 = (v.z > 0.f) | (j0 + 2 == row);
        bool p3 = (v.w > 0.f) | (j0 + 3 == row);
        int c = (int)p0 + (int)p1 + (int)p2 + (int)p3;
        int incl = c;
        #pragma unroll
        for (int d = 1; d < 32; d <<= 1) {
            int t = __shfl_up_sync(FULL, incl, d);
            if (lane >= d) incl += t;
        }
        int pos = w + incl - c;                        // exclusive
        if (p0 && pos < MAXDEG) dst[pos++] = j0;
        if (p1 && pos < MAXDEG) dst[pos++] = j0 + 1;
        if (p2 && pos < MAXDEG) dst[pos++] = j0 + 2;
        if (p3 && pos < MAXDEG) dst[pos++] = j0 + 3;
        w += __shfl_sync(FULL, incl, 31);
    }
    if (lane == 0) g_deg[row] = min(w, MAXDEG);
}

// ---------------- layer 1 linear: warp per node, all 6 heads ----------------
__global__ void k_l1_linear(const float* __restrict__ x,
                            const float* __restrict__ W1,
                            const float* __restrict__ a1) {
    __shared__ float sW[H_ * F_ * HID_];   // 12 KB
    __shared__ float sa[H_ * 2 * HID_];
    int tid = threadIdx.x;
    for (int t = tid; t < H_ * F_ * HID_; t += 256) sW[t] = W1[t];
    for (int t = tid; t < H_ * 2 * HID_;  t += 256) sa[t] = a1[t];
    __syncthreads();

    int wslot = tid >> 5, lane = tid & 31;
    int row = blockIdx.x * 8 + wslot;

    float xv = (lane < F_) ? x[(size_t)row * F_ + lane] : 0.f;
    float acc[H_] = {0.f, 0.f, 0.f, 0.f, 0.f, 0.f};
    #pragma unroll
    for (int k = 0; k < F_; k++) {
        float xk = __shfl_sync(FULL, xv, k);
        #pragma unroll
        for (int h = 0; h < H_; h++)
            acc[h] = fmaf(xk, sW[h * F_ * HID_ + k * HID_ + lane], acc[h]);
    }
    {
        __half2 h01 = __floats2half2_rn(acc[0], acc[1]);
        __half2 h23 = __floats2half2_rn(acc[2], acc[3]);
        __half2 h45 = __floats2half2_rn(acc[4], acc[5]);
        uint2 a; a.x = *(unsigned*)&h01; a.y = *(unsigned*)&h23;
        g_h1a[(size_t)row * HID_ + lane] = a;
        g_h1b[(size_t)row * HID_ + lane] = *(unsigned*)&h45;
    }
    #pragma unroll
    for (int h = 0; h < H_; h++) {
        float p1 = acc[h] * sa[h * 2 * HID_ + lane];
        float p2 = acc[h] * sa[h * 2 * HID_ + HID_ + lane];
        #pragma unroll
        for (int d = 16; d; d >>= 1) {
            p1 += __shfl_xor_sync(FULL, p1, d);
            p2 += __shfl_xor_sync(FULL, p2, d);
        }
        if (lane == 0) {
            g_s1f[h * BN_ + row] = p1;     // [h][node] layout
            g_s2f[h * BN_ + row] = p2;
        }
    }
}

// ---------------- fused layer-1 attention + ELU + layer-2 linear ----------------
// block = 512 thr = 16 warps = 16 rows of one b. Dynamic smem:
//   [0)      half  s2h[6][2048]   24576 B
//   [24576)  float sW2[192*17]    13056 B
//   [37632)  float sa2[32]          128 B
//   [37760)  float sw[16][32][8]  16384 B  (weights h0..h5, j-bits, pad; reused for x1)
#define SM1_S2  0
#define SM1_W2  24576
#define SM1_A2  37632
#define SM1_SW  37760
#define SM1_TOT 54144

__global__ void __launch_bounds__(512, 2) k_l1_attn(const float* __restrict__ W2,
                                                    const float* __restrict__ a2) {
    extern __shared__ char smem[];
    __half* s2h = (__half*)(smem + SM1_S2);
    float*  sW2 = (float*)(smem + SM1_W2);
    float*  sa2 = (float*)(smem + SM1_A2);
    float (*sw)[32][8] = (float (*)[32][8])(smem + SM1_SW);

    int tid = threadIdx.x;
    int b  = blockIdx.x >> 7;                 // 128 blocks per b
    int i0 = (blockIdx.x & 127) * 16;

    for (int t = tid; t < H_ * N_; t += 512) {
        int h = t >> 11, n = t & (N_ - 1);
        s2h[t] = __float2half(g_s2f[h * BN_ + b * N_ + n]);
    }
    for (int t = tid; t < 192 * 16; t += 512) sW2[(t >> 4) * 17 + (t & 15)] = W2[t];
    if (tid < 32) sa2[tid] = a2[tid];
    __syncthreads();

    int w = tid >> 5, lane = tid & 31;
    int i = i0 + w;
    int node_i = b * N_ + i;
    int deg = g_deg[i];
    const int* cols = g_colsP + (size_t)i * MAXDEG;

    float s1v[6];
    #pragma unroll
    for (int h = 0; h < 6; h++) s1v[h] = g_s1f[h * BN_ + node_i];

    const uint2*    fa = g_h1a + (size_t)b * N_ * HID_;
    const unsigned* fb = g_h1b + (size_t)b * N_ * HID_;

    float acc[6] = {0.f, 0.f, 0.f, 0.f, 0.f, 0.f};
    float den[6] = {0.f, 0.f, 0.f, 0.f, 0.f, 0.f};

    for (int base = 0; base < deg; base += 32) {
        int lim = min(32, deg - base);
        if (lane < lim) {
            int j = cols[base + lane];
            float wt6[6];
            #pragma unroll
            for (int h = 0; h < 6; h++) {
                float e = s1v[h] + __half2float(s2h[h * N_ + j]);
                e = e > 0.f ? e : 0.2f * e;      // LeakyReLU
                float wt = __expf(e);            // no max-shift (|e| small, fp32 safe)
                den[h] += wt;
                wt6[h] = wt;
            }
            *(float4*)&sw[w][lane][0] = make_float4(wt6[0], wt6[1], wt6[2], wt6[3]);
            *(float4*)&sw[w][lane][4] = make_float4(wt6[4], wt6[5], __int_as_float(j), 0.f);
        }
        __syncwarp();
        #define GFMA(U) {                                                  \
            float2 f0 = __half22float2(*(const __half2*)&va[U].x);         \
            float2 f1 = __half22float2(*(const __half2*)&va[U].y);         \
            float2 f2 = __half22float2(*(const __half2*)&vb[U]);           \
            acc[0] = fmaf(wA[U].x, f0.x, acc[0]);                          \
            acc[1] = fmaf(wA[U].y, f0.y, acc[1]);                          \
            acc[2] = fmaf(wA[U].z, f1.x, acc[2]);                          \
            acc[3] = fmaf(wA[U].w, f1.y, acc[3]);                          \
            acc[4] = fmaf(wB[U].x, f2.x, acc[4]);                          \
            acc[5] = fmaf(wB[U].y, f2.y, acc[5]); }
        if (lim == 32) {
            #pragma unroll
            for (int t0 = 0; t0 < 32; t0 += 8) {       // batch 8: 16 LDGs in flight
                float4 wA[8], wB[8];
                uint2 va[8]; unsigned vb[8];
                #pragma unroll
                for (int u = 0; u < 8; u++) {
                    wA[u] = *(const float4*)&sw[w][t0 + u][0];
                    wB[u] = *(const float4*)&sw[w][t0 + u][4];
                }
                #pragma unroll
                for (int u = 0; u < 8; u++) {
                    int nb = __float_as_int(wB[u].z) * HID_ + lane;
                    va[u] = fa[nb];
                    vb[u] = fb[nb];
                }
                GFMA(0) GFMA(1) GFMA(2) GFMA(3) GFMA(4) GFMA(5) GFMA(6) GFMA(7)
            }
        } else {
            for (int t0 = 0; t0 < lim; t0++) {
                float4 wA[1], wB[1];
                uint2 va[1]; unsigned vb[1];
                wA[0] = *(const float4*)&sw[w][t0][0];
                wB[0] = *(const float4*)&sw[w][t0][4];
                int nb = __float_as_int(wB[0].z) * HID_ + lane;
                va[0] = fa[nb]; vb[0] = fb[nb];
                GFMA(0)
            }
        }
        #undef GFMA
        __syncwarp();
    }
    #pragma unroll
    for (int h = 0; h < 6; h++) {
        #pragma unroll
        for (int d = 16; d; d >>= 1) den[h] += __shfl_xor_sync(FULL, den[h], d);
    }
    // ELU(x1) into the (now free) sw slice: x1[h*32+lane] = v[h]
    #pragma unroll
    for (int h = 0; h < 6; h++) {
        float v = acc[h] / den[h];
        v = v > 0.f ? v : expm1f(v);
        sw[w][lane][h] = v;
    }
    __syncwarp();

    // layer-2 linear: lane -> output o over a 96-wide k half
    int o = lane & 15, half = lane >> 4;
    int cbase = half * 96;
    float hacc = 0.f;
    #pragma unroll
    for (int c = 0; c < 96; c++) {
        int cc = cbase + c;
        hacc = fmaf(sw[w][cc & 31][cc >> 5], sW2[cc * 17 + o], hacc);
    }
    hacc += __shfl_xor_sync(FULL, hacc, 16);      // combine k-halves: all lanes have h2[o]
    if (lane < 16) g_h2h[node_i * OUT_ + o] = __float2half(hacc);

    float q1 = hacc * sa2[o];
    float q2 = hacc * sa2[OUT_ + o];
    #pragma unroll
    for (int d = 8; d; d >>= 1) {
        q1 += __shfl_xor_sync(FULL, q1, d, 16);
        q2 += __shfl_xor_sync(FULL, q2, d, 16);
    }
    if (lane == 0) {
        g_t1[node_i] = q1;
        g_t2[node_i] = q2;
    }
}

// ---------------- layer-2 attention: lane-per-neighbor, register accumulators ----------------
#define L2W 8
__global__ void __launch_bounds__(256) k_l2_attn(float* __restrict__ out) {
    __shared__ float red[L2W][16 * 33];    // padded transpose for final reduction (16.5 KB)
    int w = threadIdx.x >> 5, lane = threadIdx.x & 31;
    int gw = blockIdx.x * L2W + w;          // warp per (b, i)
    int i = gw & (N_ - 1), b = gw >> 11;
    int node_i = b * N_ + i;
    int deg = g_deg[i];
    const int* cols = g_colsP + (size_t)i * MAXDEG;
    float s1i = g_t1[node_i];
    const float* t2b = g_t2 + b * N_;
    const uint4* h2b = (const uint4*)(g_h2h + (size_t)b * N_ * OUT_);

    float acc[16];
    #pragma unroll
    for (int o = 0; o < 16; o++) acc[o] = 0.f;
    float den = 0.f;

    for (int t = lane; t < deg; t += 32) {   // each lane owns its neighbors
        int j = __ldg(cols + t);
        float e = s1i + __ldg(t2b + j);
        e = e > 0.f ? e : 0.2f * e;          // LeakyReLU
        float wt = __expf(e);
        den += wt;
        uint4 va = __ldg(h2b + j * 2);
        uint4 vb = __ldg(h2b + j * 2 + 1);
        float2 f;
        f = __half22float2(*(const __half2*)&va.x); acc[0]  = fmaf(wt, f.x, acc[0]);  acc[1]  = fmaf(wt, f.y, acc[1]);
        f = __half22float2(*(const __half2*)&va.y); acc[2]  = fmaf(wt, f.x, acc[2]);  acc[3]  = fmaf(wt, f.y, acc[3]);
        f = __half22float2(*(const __half2*)&va.z); acc[4]  = fmaf(wt, f.x, acc[4]);  acc[5]  = fmaf(wt, f.y, acc[5]);
        f = __half22float2(*(const __half2*)&va.w); acc[6]  = fmaf(wt, f.x, acc[6]);  acc[7]  = fmaf(wt, f.y, acc[7]);
        f = __half22float2(*(const __half2*)&vb.x); acc[8]  = fmaf(wt, f.x, acc[8]);  acc[9]  = fmaf(wt, f.y, acc[9]);
        f = __half22float2(*(const __half2*)&vb.y); acc[10] = fmaf(wt, f.x, acc[10]); acc[11] = fmaf(wt, f.y, acc[11]);
        f = __half22float2(*(const __half2*)&vb.z); acc[12] = fmaf(wt, f.x, acc[12]); acc[13] = fmaf(wt, f.y, acc[13]);
        f = __half22float2(*(const __half2*)&vb.w); acc[14] = fmaf(wt, f.x, acc[14]); acc[15] = fmaf(wt, f.y, acc[15]);
    }
    #pragma unroll
    for (int d = 16; d; d >>= 1) den += __shfl_xor_sync(FULL, den, d);

    // transpose-reduce: lane writes its 16 accs, then 16 lanes sum 32 each
    float* rw = red[w];
    #pragma unroll
    for (int o = 0; o < 16; o++) rw[o * 33 + lane] = acc[o];
    __syncwarp();
    if (lane < 16) {
        float s = 0.f;
        #pragma unroll
        for (int k = 0; k < 32; k++) s += rw[lane * 33 + k];
        float v = s / den;
        v = v > 0.f ? v : expm1f(v);          // ELU
        out[(size_t)node_i * OUT_ + lane] = v;
    }
}

// ---------------- launch ----------------
extern "C" void kernel_launch(void* const* d_in, const int* in_sizes, int n_in,
                              void* d_out, int out_size) {
    const float* flow_x = (const float*)d_in[0];   // [4,2048,16]
    const float* adj    = (const float*)d_in[1];   // [2048,2048]
    const float* W1     = (const float*)d_in[2];   // [6,16,32]
    const float* a1     = (const float*)d_in[3];   // [6,64,1]
    const float* W2     = (const float*)d_in[4];   // [192,16]
    const float* a2     = (const float*)d_in[5];   // [32,1]
    float* out = (float*)d_out;

    cudaFuncSetAttribute(k_l1_attn, cudaFuncAttributeMaxDynamicSharedMemorySize, SM1_TOT);

    k_build<<<N_ / 8, 256>>>(adj);
    k_l1_linear<<<BN_ / 8, 256>>>(flow_x, W1, a1);
    k_l1_attn<<<BN_ / 16, 512, SM1_TOT>>>(W2, a2);
    k_l2_attn<<<BN_ / L2W, 256>>>(out);
}